// round 3
// baseline (speedup 1.0000x reference)
#include <cuda_runtime.h>
#include <cuda_bf16.h>
#include <cstdint>

// Problem constants
#define BB   64
#define LL   1024
#define ENC  512
#define ATTN 512
#define STRH 256
#define CELLH 512

// ---------------- scratch (no allocations allowed) ----------------
__device__ float g_bias[BB * ATTN];     // per-(b,a) bias = b_enc + a_str + a_cell
__device__ float g_scores[BB * LL];     // pre-softmax scores

// ---------------- f32x2 packed-FMA helpers (sm_100+) ----------------
__device__ __forceinline__ unsigned long long pack2(float x, float y) {
    unsigned long long r;
    asm("mov.b64 %0, {%1, %2};" : "=l"(r) : "f"(x), "f"(y));
    return r;
}
__device__ __forceinline__ void unpack2(unsigned long long v, float& lo, float& hi) {
    asm("mov.b64 {%0, %1}, %2;" : "=f"(lo), "=f"(hi) : "l"(v));
}
__device__ __forceinline__ void ffma2(unsigned long long& d, unsigned long long a,
                                      unsigned long long b) {
    asm("fma.rn.f32x2 %0, %1, %2, %0;" : "+l"(d) : "l"(a), "l"(b));
}

// =====================================================================
// Kernel A: bias[b][a] = b_enc[a] + str[b]@W_str[:,a] + b_str[a]
//                       + cell[b]@W_cell[:,a] + b_cell[a]
// grid = 64 blocks (b), 512 threads (a)
// =====================================================================
__global__ __launch_bounds__(512)
void bias_kernel(const float* __restrict__ str, const float* __restrict__ cell,
                 const float* __restrict__ Wstr, const float* __restrict__ bstr,
                 const float* __restrict__ Wcell, const float* __restrict__ bcell,
                 const float* __restrict__ benc)
{
    __shared__ float sh[STRH + CELLH];
    const int b = blockIdx.x;
    const int a = threadIdx.x;

    if (a < STRH) sh[a] = str[b * STRH + a];
    sh[STRH + a] = cell[b * CELLH + a];
    __syncthreads();

    float acc = benc[a] + bstr[a] + bcell[a];
#pragma unroll 8
    for (int e = 0; e < STRH; ++e)
        acc += sh[e] * Wstr[e * ATTN + a];
#pragma unroll 8
    for (int e = 0; e < CELLH; ++e)
        acc += sh[STRH + e] * Wcell[e * ATTN + a];

    g_bias[b * ATTN + a] = acc;
}

// =====================================================================
// Kernel B: fused GEMM + relu + W_comb reduction -> scores[b][l]
//   scores[b][l] = sum_a relu( x[b,l,:]@W_enc[:,a] + bias[b][a] ) * Wc[a] + b_comb
// Block tile: 64 L-rows x 128 N-cols per chunk (4 chunks cover ATTN=512), K=512.
// 256 threads, thread microtile 4(m) x 8(n) via f32x2 (m-pairs packed).
// x tile kept transposed in smem for the whole block; W double-buffered.
// =====================================================================
#define XT_STRIDE 66                    // 64 + 2 pad (even -> 8B-aligned LDS.64)
#define SM_XT     0                     // 512 * 66 floats
#define SM_WT     (512 * XT_STRIDE)     // 2 * 64 * 128 floats
#define SM_BIAS   (SM_WT + 2 * 64 * 128)
#define SM_WC     (SM_BIAS + ATTN)
#define SM_RED    (SM_WC + ATTN)        // 64 * 17 floats
#define SMEM_B_FLOATS (SM_RED + 64 * 17)
#define SMEM_B_BYTES  (SMEM_B_FLOATS * 4)   // 209,220 B < 227 KB

__global__ __launch_bounds__(256, 1)
void scores_kernel(const float* __restrict__ x, const float* __restrict__ W,
                   const float* __restrict__ Wc, const float* __restrict__ bcomb)
{
    extern __shared__ float sm[];
    float* xT     = sm + SM_XT;    // [512][XT_STRIDE]  (k-major, m contiguous)
    float* Wt     = sm + SM_WT;    // [2][64][128]
    float* bias_s = sm + SM_BIAS;  // [512]
    float* wc_s   = sm + SM_WC;    // [512]
    float* red    = sm + SM_RED;   // [64][17]

    const int b   = blockIdx.y;
    const int l0  = blockIdx.x * 64;
    const int tid = threadIdx.x;

    // ---- load x tile transposed: xT[e][m] = x[b][l0+m][e] ----
    const float4* xg = reinterpret_cast<const float4*>(
        x + ((size_t)b * LL + l0) * ENC);
#pragma unroll
    for (int it = 0; it < 32; ++it) {            // 64*128 float4 / 256 threads
        int idx = tid + it * 256;
        int l = idx >> 7;                         // 0..63
        int e4 = idx & 127;                       // 0..127
        float4 v = xg[l * 128 + e4];
        int e = e4 * 4;
        xT[(e + 0) * XT_STRIDE + l] = v.x;
        xT[(e + 1) * XT_STRIDE + l] = v.y;
        xT[(e + 2) * XT_STRIDE + l] = v.z;
        xT[(e + 3) * XT_STRIDE + l] = v.w;
    }
    // ---- bias / Wc into smem ----
#pragma unroll
    for (int i = tid; i < ATTN; i += 256) {
        bias_s[i] = g_bias[b * ATTN + i];
        wc_s[i]   = Wc[i];
    }

    const int ty = tid >> 4;          // 0..15  -> m group
    const int tx = tid & 15;          // 0..15  -> n group
    const int m0 = ty * 4;

    float s0 = 0.f, s1 = 0.f, s2 = 0.f, s3 = 0.f;

    const float4* Wg4 = reinterpret_cast<const float4*>(W);
    // per-thread W-load coordinates (64kk x 32 float4 tile, 8 loads/thread)
    int kk_p[8], n4_p[8];
#pragma unroll
    for (int j = 0; j < 8; ++j) {
        int idx = tid + j * 256;
        kk_p[j] = idx >> 5;           // 0..63
        n4_p[j] = idx & 31;           // 0..31
    }

    for (int nc = 0; nc < 4; ++nc) {
        const int N0  = nc * 128;
        const int N04 = N0 >> 2;

        // initial W ktile -> buf 0
        {
            float4* dst = reinterpret_cast<float4*>(Wt);
#pragma unroll
            for (int j = 0; j < 8; ++j)
                dst[kk_p[j] * 32 + n4_p[j]] =
                    Wg4[(size_t)kk_p[j] * 128 + N04 + n4_p[j]];
        }
        __syncthreads();   // first nc: also covers xT/bias/wc stores

        unsigned long long acc[2][8];
#pragma unroll
        for (int i = 0; i < 2; ++i)
#pragma unroll
            for (int j = 0; j < 8; ++j) acc[i][j] = 0ull;

        for (int t = 0; t < 8; ++t) {
            // prefetch next W ktile into registers
            float4 pre[8];
            if (t < 7) {
#pragma unroll
                for (int j = 0; j < 8; ++j)
                    pre[j] = Wg4[((size_t)(t + 1) * 64 + kk_p[j]) * 128 + N04 + n4_p[j]];
            }

            const float* Wb = Wt + (t & 1) * 8192;
#pragma unroll 8
            for (int kk = 0; kk < 64; ++kk) {
                const float* xr = xT + (t * 64 + kk) * XT_STRIDE + m0;
                unsigned long long a01 = *reinterpret_cast<const unsigned long long*>(xr);
                unsigned long long a23 = *reinterpret_cast<const unsigned long long*>(xr + 2);
                const float* wr = Wb + kk * 128 + tx * 4;
                float4 w0 = *reinterpret_cast<const float4*>(wr);
                float4 w1 = *reinterpret_cast<const float4*>(wr + 64);
                unsigned long long wd;
                wd = pack2(w0.x, w0.x); ffma2(acc[0][0], a01, wd); ffma2(acc[1][0], a23, wd);
                wd = pack2(w0.y, w0.y); ffma2(acc[0][1], a01, wd); ffma2(acc[1][1], a23, wd);
                wd = pack2(w0.z, w0.z); ffma2(acc[0][2], a01, wd); ffma2(acc[1][2], a23, wd);
                wd = pack2(w0.w, w0.w); ffma2(acc[0][3], a01, wd); ffma2(acc[1][3], a23, wd);
                wd = pack2(w1.x, w1.x); ffma2(acc[0][4], a01, wd); ffma2(acc[1][4], a23, wd);
                wd = pack2(w1.y, w1.y); ffma2(acc[0][5], a01, wd); ffma2(acc[1][5], a23, wd);
                wd = pack2(w1.z, w1.z); ffma2(acc[0][6], a01, wd); ffma2(acc[1][6], a23, wd);
                wd = pack2(w1.w, w1.w); ffma2(acc[0][7], a01, wd); ffma2(acc[1][7], a23, wd);
            }

            if (t < 7) {
                float4* dst = reinterpret_cast<float4*>(Wt + ((t + 1) & 1) * 8192);
#pragma unroll
                for (int j = 0; j < 8; ++j)
                    dst[kk_p[j] * 32 + n4_p[j]] = pre[j];
                __syncthreads();
            }
        }

        // epilogue: relu(p + bias) * Wc, accumulate per-m partial score
#pragma unroll
        for (int i = 0; i < 2; ++i) {
#pragma unroll
            for (int jj = 0; jj < 8; ++jj) {
                float plo, phi;
                unpack2(acc[i][jj], plo, phi);
                int n = N0 + ((jj < 4) ? (tx * 4 + jj) : (64 + tx * 4 + jj - 4));
                float bn = bias_s[n], wn = wc_s[n];
                float t0 = fmaxf(plo + bn, 0.0f) * wn;
                float t1 = fmaxf(phi + bn, 0.0f) * wn;
                if (i == 0) { s0 += t0; s1 += t1; }
                else        { s2 += t0; s3 += t1; }
            }
        }
        // no sync needed here: next nc writes buf0 (disjoint from buf1 readers)
        // and syncs before compute.
    }

    // cross-tx reduction of partial scores
    red[(m0 + 0) * 17 + tx] = s0;
    red[(m0 + 1) * 17 + tx] = s1;
    red[(m0 + 2) * 17 + tx] = s2;
    red[(m0 + 3) * 17 + tx] = s3;
    __syncthreads();
    if (tid < 64) {
        float sum = 0.f;
#pragma unroll
        for (int j = 0; j < 16; ++j) sum += red[tid * 17 + j];
        g_scores[b * LL + l0 + tid] = sum + bcomb[0];
    }
}

// =====================================================================
// Kernel C: softmax over L (per b) + weighted sum -> context[b][e]
// grid = (8 e-chunks, 64 b), 256 threads
// =====================================================================
__global__ __launch_bounds__(256)
void ctx_kernel(const float* __restrict__ x, float* __restrict__ out)
{
    __shared__ float sc[LL];
    __shared__ float redw[16];          // [0..7] max partials, [8..15] sum partials
    __shared__ float part[4][64];

    const int b   = blockIdx.y;
    const int e0  = blockIdx.x * 64;
    const int tid = threadIdx.x;
    const int lane = tid & 31, wid = tid >> 5;

    // load scores, local max
    float lmax = -1e30f;
#pragma unroll
    for (int i = tid; i < LL; i += 256) {
        float v = g_scores[b * LL + i];
        sc[i] = v;
        lmax = fmaxf(lmax, v);
    }
#pragma unroll
    for (int off = 16; off > 0; off >>= 1)
        lmax = fmaxf(lmax, __shfl_xor_sync(0xffffffffu, lmax, off));
    if (lane == 0) redw[wid] = lmax;
    __syncthreads();
    float gmax = redw[0];
#pragma unroll
    for (int j = 1; j < 8; ++j) gmax = fmaxf(gmax, redw[j]);

    // exp + local sum
    float lsum = 0.f;
#pragma unroll
    for (int i = tid; i < LL; i += 256) {
        float e = __expf(sc[i] - gmax);
        sc[i] = e;
        lsum += e;
    }
#pragma unroll
    for (int off = 16; off > 0; off >>= 1)
        lsum += __shfl_xor_sync(0xffffffffu, lsum, off);
    if (lane == 0) redw[8 + wid] = lsum;
    __syncthreads();
    float gsum = 0.f;
#pragma unroll
    for (int j = 0; j < 8; ++j) gsum += redw[8 + j];
    const float inv = 1.0f / gsum;

    // weighted sum over L for this e-chunk
    const int el = tid & 63;
    const int lg = tid >> 6;            // 0..3
    const float* xp = x + (size_t)b * LL * ENC + e0 + el;
    float acc = 0.f;
#pragma unroll 8
    for (int l = lg; l < LL; l += 4)
        acc += sc[l] * xp[(size_t)l * ENC];

    part[lg][el] = acc;
    __syncthreads();
    if (tid < 64)
        out[b * ENC + e0 + tid] =
            (part[0][tid] + part[1][tid] + part[2][tid] + part[3][tid]) * inv;
}

// =====================================================================
extern "C" void kernel_launch(void* const* d_in, const int* in_sizes, int n_in,
                              void* d_out, int out_size)
{
    const float* x      = (const float*)d_in[0];
    const float* str    = (const float*)d_in[1];
    const float* cell   = (const float*)d_in[2];
    const float* W_enc  = (const float*)d_in[3];
    const float* b_enc  = (const float*)d_in[4];
    const float* W_str  = (const float*)d_in[5];
    const float* b_str  = (const float*)d_in[6];
    const float* W_cell = (const float*)d_in[7];
    const float* b_cell = (const float*)d_in[8];
    const float* W_comb = (const float*)d_in[9];
    const float* b_comb = (const float*)d_in[10];
    float* out = (float*)d_out;

    cudaFuncSetAttribute(scores_kernel,
                         cudaFuncAttributeMaxDynamicSharedMemorySize, SMEM_B_BYTES);

    bias_kernel<<<BB, 512>>>(str, cell, W_str, b_str, W_cell, b_cell, b_enc);
    scores_kernel<<<dim3(LL / 64, BB), 256, SMEM_B_BYTES>>>(x, W_enc, W_comb, b_comb);
    ctx_kernel<<<dim3(ENC / 64, BB), 256>>>(x, out);
}